// round 16
// baseline (speedup 1.0000x reference)
#include <cuda_runtime.h>
#include <cuda_fp16.h>
#include <mma.h>

using namespace nvcuda;

#define NN 500000
#define EE 2000000
#define GG 64
#define EPS 1e-5f
#define SCAN_B 512
#define NBS ((NN + SCAN_B - 1) / SCAN_B)   // 977
#define NBD ((EE + 255) / 256)             // 7813
#define NTILES ((NN + 127) / 128)          // 3907
#define F1_BLOCKS 1184

// ---------------- scratch (device globals; no allocs allowed) ----------------
__device__ __align__(16) int    g_deg[NN];
__device__ __align__(16) float  g_dis[NN];
__device__ __align__(16) int2   g_dc[NN];
__device__ __align__(16) int    g_off[NN + 1];
__device__ __align__(16) int    g_cur[NN];
__device__ __align__(16) int    g_bsum[NBS];
__device__ __align__(16) int    g_srcs[EE];
__device__ __align__(16) float  g_S[NN * 9];
__device__ __align__(16) __half g_y1[((size_t)NN + 128) * 64];  // dis*(z1@W2) fp16
__device__ __align__(16) __half g_y[(size_t)NN * 64];
__device__ __align__(16) float  g_M1[9 * 64];
__device__ __align__(16) float  g_mom[64];
__device__ __align__(16) float  g_q2[64];
__device__ __align__(16) float  g_psum[GG * 64];
__device__ __align__(16) int    g_pmax[GG * 64];
__device__ __align__(16) int    g_pmin[GG * 64];
__device__                int    g_cnt[GG];

// ---------------- helpers ----------------
__device__ __forceinline__ void atomicMaxFloat(int* addr, float v) {
    if (v >= 0.0f) atomicMax(addr, __float_as_int(v));
    else           atomicMin((unsigned int*)addr, __float_as_uint(v));
}
__device__ __forceinline__ void atomicMinFloat(int* addr, float v) {
    if (v >= 0.0f) atomicMin(addr, __float_as_int(v));
    else           atomicMax((unsigned int*)addr, __float_as_uint(v));
}
__device__ __forceinline__ void acc8(float* a, uint4 r) {
    float2 q0 = __half22float2(*(half2*)&r.x);
    float2 q1 = __half22float2(*(half2*)&r.y);
    float2 q2 = __half22float2(*(half2*)&r.z);
    float2 q3 = __half22float2(*(half2*)&r.w);
    a[0] += q0.x; a[1] += q0.y; a[2] += q1.x; a[3] += q1.y;
    a[4] += q2.x; a[5] += q2.y; a[6] += q3.x; a[7] += q3.y;
}
// packed f32x2 (sm_100+, PTX 8.6) — exact fp32 arithmetic, 2 lanes per inst
__device__ __forceinline__ unsigned long long pk2(float x, float y) {
    unsigned long long r;
    asm("mov.b64 %0, {%1, %2};" : "=l"(r) : "f"(x), "f"(y));
    return r;
}
__device__ __forceinline__ void upk2(unsigned long long v, float& x, float& y) {
    asm("mov.b64 {%0, %1}, %2;" : "=f"(x), "=f"(y) : "l"(v));
}
__device__ __forceinline__ unsigned long long fma2_(unsigned long long a,
                                                    unsigned long long b,
                                                    unsigned long long c) {
    unsigned long long d;
    asm("fma.rn.f32x2 %0, %1, %2, %3;" : "=l"(d) : "l"(a), "l"(b), "l"(c));
    return d;
}
__device__ __forceinline__ unsigned long long mul2_(unsigned long long a,
                                                    unsigned long long b) {
    unsigned long long d;
    asm("mul.rn.f32x2 %0, %1, %2;" : "=l"(d) : "l"(a), "l"(b));
    return d;
}

// ======= degree histogram + all small init + cnt + M1 prep ===================
__global__ void k_init_deg(const int* __restrict__ edst,
                           const int* __restrict__ batch,
                           const float* __restrict__ emb_type,
                           const float* __restrict__ emb_inv,
                           const float* __restrict__ W1) {
    int b = blockIdx.x;
    int tid = threadIdx.x;
    if (b < NBD) {
        int e = b * 256 + tid;
        if (e < EE) atomicAdd(&g_deg[edst[e]], 1);
        return;
    }
    int extra = b - NBD;
    if (extra == 0) {
        for (int i = tid; i < GG * 64; i += 256) {
            g_pmax[i] = 0xFF800000;
            g_pmin[i] = 0x7F800000;
            g_psum[i] = 0.0f;
        }
        if (tid < 64) { g_mom[tid] = 0.0f; g_q2[tid] = 0.0f; }
    } else if (extra == 1) {
        int g = tid;
        if (g < GG) {
            int lo0 = 0, hi0 = NN;
            while (lo0 < hi0) { int m = (lo0 + hi0) >> 1; if (batch[m] < g) lo0 = m + 1; else hi0 = m; }
            int lo1 = lo0, hi1 = NN;
            while (lo1 < hi1) { int m = (lo1 + hi1) >> 1; if (batch[m] < g + 1) lo1 = m + 1; else hi1 = m; }
            g_cnt[g] = lo1 - lo0;
        }
    } else {
        for (int t = tid; t < 9 * 64; t += 256) {
            int combo = t >> 6;
            int f = t & 63;
            int ty = combo / 3, iv = combo % 3;
            float acc = 0.0f;
#pragma unroll
            for (int k = 0; k < 16; k++) {
                acc = fmaf(emb_type[ty * 16 + k], W1[k * 64 + f], acc);
                acc = fmaf(emb_inv[iv * 16 + k], W1[(16 + k) * 64 + f], acc);
            }
            g_M1[combo * 64 + f] = acc;
        }
    }
}

// ======= per-node dis/dc/S-row + block-scan of deg (scan stage 1) ============
__global__ __launch_bounds__(SCAN_B) void k_dis_scan1(const int* __restrict__ node_type,
                                                      const int* __restrict__ num_inv) {
    __shared__ int s[SCAN_B];
    int gid = blockIdx.x * SCAN_B + threadIdx.x;
    int dval = (gid < NN) ? g_deg[gid] : 0;
    if (gid < NN) {
        int d = dval + 1;
        float dis = rsqrtf((float)d);
        g_dis[gid] = dis;
        int c = node_type[gid] * 3 + num_inv[gid];
        g_dc[gid] = make_int2(__float_as_int(dis), c);
        float id = dis * dis;
#pragma unroll
        for (int t = 0; t < 9; t++) g_S[(size_t)gid * 9 + t] = (t == c) ? id : 0.0f;
    }
    s[threadIdx.x] = dval;
    __syncthreads();
    for (int o = 1; o < SCAN_B; o <<= 1) {
        int x = s[threadIdx.x];
        if (threadIdx.x >= o) x += s[threadIdx.x - o];
        __syncthreads();
        s[threadIdx.x] = x;
        __syncthreads();
    }
    if (threadIdx.x == SCAN_B - 1) g_bsum[blockIdx.x] = s[SCAN_B - 1];
}

// ======= fused scan stages 2+3 ===============================================
__global__ __launch_bounds__(SCAN_B) void k_scan23() {
    __shared__ int s[SCAN_B];
    __shared__ int red[SCAN_B];
    int acc = 0;
    for (int j = threadIdx.x; j < blockIdx.x; j += SCAN_B) acc += g_bsum[j];
    red[threadIdx.x] = acc;
    __syncthreads();
    for (int o = SCAN_B / 2; o > 0; o >>= 1) {
        if ((int)threadIdx.x < o) red[threadIdx.x] += red[threadIdx.x + o];
        __syncthreads();
    }
    int bpre = red[0];

    int gid = blockIdx.x * SCAN_B + threadIdx.x;
    int dval = (gid < NN) ? g_deg[gid] : 0;
    s[threadIdx.x] = dval;
    __syncthreads();
    for (int o = 1; o < SCAN_B; o <<= 1) {
        int x = s[threadIdx.x];
        if (threadIdx.x >= o) x += s[threadIdx.x - o];
        __syncthreads();
        s[threadIdx.x] = x;
        __syncthreads();
    }
    if (gid < NN) {
        int excl = s[threadIdx.x] - dval + bpre;
        g_off[gid] = excl;
        g_cur[gid] = excl;
        if (gid == NN - 1) g_off[NN] = excl + dval;
    }
}

// ======= CSR ticket-scatter + layer-1 bucket aggregation =====================
__global__ void k_scatter_edge1(const int* __restrict__ esrc, const int* __restrict__ edst) {
    int e = blockIdx.x * blockDim.x + threadIdx.x;
    if (e >= EE) return;
    int s = esrc[e], d = edst[e];
    int2 ds = __ldg(&g_dc[s]);
    int2 dd = __ldg(&g_dc[d]);
    int pos = atomicAdd(&g_cur[d], 1);
    g_srcs[pos] = s;
    atomicAdd(&g_S[(size_t)d * 9 + ds.y], __int_as_float(ds.x) * __int_as_float(dd.x));
}

// ======= S moments ============================================================
__global__ __launch_bounds__(256) void k_stats() {
    __shared__ float sS[256 * 9];
    __shared__ float sred[8][54];
    float m[54];
#pragma unroll
    for (int i = 0; i < 54; i++) m[i] = 0.0f;

    int tiles = (NN + 255) / 256;
    for (int t = blockIdx.x; t < tiles; t += gridDim.x) {
        int base = t * 256;
        int cnt = min(256, NN - base);
        int tot = cnt * 9;
        __syncthreads();
        for (int i = threadIdx.x; i < tot; i += 256) sS[i] = g_S[(size_t)base * 9 + i];
        __syncthreads();
        if ((int)threadIdx.x < cnt) {
            float r[9];
#pragma unroll
            for (int j = 0; j < 9; j++) r[j] = sS[threadIdx.x * 9 + j];
            int k = 9;
#pragma unroll
            for (int i = 0; i < 9; i++) {
                m[i] += r[i];
#pragma unroll
                for (int j = i; j < 9; j++) { m[k] = fmaf(r[i], r[j], m[k]); k++; }
            }
        }
    }
#pragma unroll
    for (int v = 0; v < 54; v++) {
#pragma unroll
        for (int o = 16; o > 0; o >>= 1) m[v] += __shfl_down_sync(0xffffffffu, m[v], o);
    }
    int lane = threadIdx.x & 31, warp = threadIdx.x >> 5;
    if (lane == 0) {
#pragma unroll
        for (int v = 0; v < 54; v++) sred[warp][v] = m[v];
    }
    __syncthreads();
    if (threadIdx.x < 54) {
        float acc = 0.0f;
#pragma unroll
        for (int w = 0; w < 8; w++) acc += sred[w][threadIdx.x];
        atomicAdd(&g_mom[threadIdx.x], acc);
    }
}

// ======= fused BN1 + layer1(f32x2) + wmma GEMM -> y1' fp16 ===================
// Per-element build cost halved via packed fma.rn.f32x2 (exact fp32).
#define ZLD 80
__global__ __launch_bounds__(256) void k_fused1(const float* __restrict__ W2,
                                                const float* __restrict__ gamma1,
                                                const float* __restrict__ beta1) {
    __shared__ __align__(16) float  sM1[9 * 64];
    __shared__ __align__(16) float  sA[64], sSh[64];
    __shared__ __half sW[64 * 64];
    __shared__ __half sZ[128 * ZLD];

    int tid = threadIdx.x;
    for (int i = tid; i < 9 * 64; i += 256) sM1[i] = g_M1[i];
    for (int i = tid; i < 64 * 64 / 2; i += 256) {
        float2 w = ((const float2*)W2)[i];
        ((half2*)sW)[i] = __floats2half2_rn(w.x, w.y);
    }
    __syncthreads();

    if (tid < 64) {
        int f = tid;
        float mcol[9];
#pragma unroll
        for (int t = 0; t < 9; t++) mcol[t] = sM1[t * 64 + f];
        float mean = 0.0f;
#pragma unroll
        for (int t = 0; t < 9; t++) mean = fmaf(g_mom[t], mcol[t], mean);
        mean /= (float)NN;
        float e2 = 0.0f;
        int k = 9;
#pragma unroll
        for (int i = 0; i < 9; i++) {
#pragma unroll
            for (int j = i; j < 9; j++) {
                float term = g_mom[k++] * mcol[i] * mcol[j];
                e2 += (i == j) ? term : 2.0f * term;
            }
        }
        e2 /= (float)NN;
        float var = e2 - mean * mean;
        float a = rsqrtf(var + EPS) * gamma1[f];
        sA[f] = a;
        sSh[f] = beta1[f] - mean * a;
    }
    __syncthreads();

    int nl = tid >> 1;
    int h = tid & 1;
    int w = tid >> 5;

    for (int t = blockIdx.x; t < NTILES; t += gridDim.x) {
        int base = t * 128;
        __syncthreads();   // protect sZ from previous tile's wmma readers
        {
            int v = base + nl;
            half2* dst = (half2*)(sZ + nl * ZLD + h * 32);
            if (v < NN) {
                float dv = g_dis[v];
                unsigned long long dvb = pk2(dv, dv);
                const float* Srow = g_S + (size_t)v * 9;
                unsigned long long acc[16];
#pragma unroll
                for (int j = 0; j < 16; j++) acc[j] = 0ull;
#pragma unroll
                for (int tt = 0; tt < 9; tt++) {
                    float sv = Srow[tt];
                    unsigned long long svb = pk2(sv, sv);
                    const unsigned long long* M2 =
                        (const unsigned long long*)(sM1 + tt * 64 + h * 32);
#pragma unroll
                    for (int j = 0; j < 16; j++) acc[j] = fma2_(svb, M2[j], acc[j]);
                }
                const unsigned long long* A2 = (const unsigned long long*)(sA + h * 32);
                const unsigned long long* S2 = (const unsigned long long*)(sSh + h * 32);
#pragma unroll
                for (int j = 0; j < 16; j++) {
                    unsigned long long z = fma2_(acc[j], A2[j], S2[j]);
                    z = mul2_(z, dvb);           // dv*relu(x) == relu(dv*x), dv>0
                    float lo, hi;
                    upk2(z, lo, hi);
                    dst[j] = __floats2half2_rn(fmaxf(lo, 0.f), fmaxf(hi, 0.f));
                }
            } else {
#pragma unroll
                for (int j = 0; j < 16; j++) dst[j] = __floats2half2_rn(0.f, 0.f);
            }
        }
        __syncthreads();

        wmma::fragment<wmma::accumulator, 16, 16, 16, float> cf[4];
#pragma unroll
        for (int n = 0; n < 4; n++) wmma::fill_fragment(cf[n], 0.0f);
#pragma unroll
        for (int k = 0; k < 4; k++) {
            wmma::fragment<wmma::matrix_a, 16, 16, 16, __half, wmma::row_major> af;
            wmma::load_matrix_sync(af, sZ + (w * 16) * ZLD + k * 16, ZLD);
#pragma unroll
            for (int n = 0; n < 4; n++) {
                wmma::fragment<wmma::matrix_b, 16, 16, 16, __half, wmma::row_major> bf;
                wmma::load_matrix_sync(bf, sW + (k * 16) * 64 + n * 16, 64);
                wmma::mma_sync(cf[n], af, bf, cf[n]);
            }
        }
#pragma unroll
        for (int n = 0; n < 4; n++) {
            wmma::fragment<wmma::accumulator, 16, 16, 16, __half> ch;
#pragma unroll
            for (int i = 0; i < cf[n].num_elements; i++) ch.x[i] = __float2half(cf[n].x[i]);
            wmma::store_matrix_sync(g_y1 + ((size_t)base + w * 16) * 64 + n * 16, ch, 64,
                                    wmma::mem_row_major);
        }
    }
}

// ======= CSR gather — 4 nodes/warp, MLP-4 batched row loads ==================
__global__ __launch_bounds__(256) void k_gather() {
    int lane = threadIdx.x & 31;
    int sub = lane & 7;
    int grp = lane >> 3;
    int gw = (blockIdx.x * blockDim.x + threadIdx.x) >> 5;
    int nw = (gridDim.x * blockDim.x) >> 5;

    for (int v = gw * 4 + grp; v < NN; v += nw * 4) {
        uint4 raw = ((const uint4*)(g_y1 + (size_t)v * 64))[sub];
        int off0 = __ldg(&g_off[v]), off1 = __ldg(&g_off[v + 1]);
        float a[8];
        float2 p0 = __half22float2(*(half2*)&raw.x);
        float2 p1 = __half22float2(*(half2*)&raw.y);
        float2 p2 = __half22float2(*(half2*)&raw.z);
        float2 p3 = __half22float2(*(half2*)&raw.w);
        a[0] = p0.x; a[1] = p0.y; a[2] = p1.x; a[3] = p1.y;
        a[4] = p2.x; a[5] = p2.y; a[6] = p3.x; a[7] = p3.y;

        int i = off0;
        for (; i + 3 < off1; i += 4) {
            int s0 = __ldg(&g_srcs[i]);
            int s1 = __ldg(&g_srcs[i + 1]);
            int s2 = __ldg(&g_srcs[i + 2]);
            int s3 = __ldg(&g_srcs[i + 3]);
            uint4 r0 = ((const uint4*)(g_y1 + (size_t)s0 * 64))[sub];
            uint4 r1 = ((const uint4*)(g_y1 + (size_t)s1 * 64))[sub];
            uint4 r2 = ((const uint4*)(g_y1 + (size_t)s2 * 64))[sub];
            uint4 r3 = ((const uint4*)(g_y1 + (size_t)s3 * 64))[sub];
            acc8(a, r0); acc8(a, r1); acc8(a, r2); acc8(a, r3);
        }
        if (i + 1 < off1) {
            int s0 = __ldg(&g_srcs[i]);
            int s1 = __ldg(&g_srcs[i + 1]);
            uint4 r0 = ((const uint4*)(g_y1 + (size_t)s0 * 64))[sub];
            uint4 r1 = ((const uint4*)(g_y1 + (size_t)s1 * 64))[sub];
            acc8(a, r0); acc8(a, r1);
            i += 2;
        }
        if (i < off1) {
            int s0 = __ldg(&g_srcs[i]);
            uint4 r0 = ((const uint4*)(g_y1 + (size_t)s0 * 64))[sub];
            acc8(a, r0);
        }

        float dv = g_dis[v];
        half2 h0 = __floats2half2_rn(dv * a[0], dv * a[1]);
        half2 h1 = __floats2half2_rn(dv * a[2], dv * a[3]);
        half2 h2 = __floats2half2_rn(dv * a[4], dv * a[5]);
        half2 h3 = __floats2half2_rn(dv * a[6], dv * a[7]);
        int4 out;
        out.x = *(int*)&h0; out.y = *(int*)&h1;
        out.z = *(int*)&h2; out.w = *(int*)&h3;
        __stcs((int4*)(g_y + (size_t)v * 64) + sub, out);
    }
}

// ======= vectorized pool: 8 feats/lane, half2 max/min, BN2 sq ================
__global__ __launch_bounds__(256) void k_pool(const int* __restrict__ batch) {
    int lane = threadIdx.x & 31;
    int sub = lane & 7;
    int gidx = (blockIdx.x * blockDim.x + threadIdx.x) >> 3;
    int ngroups = (gridDim.x * blockDim.x) >> 3;
    int npg = (NN + ngroups - 1) / ngroups;
    int v0 = gidx * npg;
    int v1 = min(v0 + npg, NN);

    float psum[8], sq[8];
    unsigned mx[4], mn[4];
#pragma unroll
    for (int j = 0; j < 8; j++) { psum[j] = 0.f; sq[j] = 0.f; }
#pragma unroll
    for (int j = 0; j < 4; j++) { mx[j] = 0xFC00FC00u; mn[j] = 0x7C007C00u; }
    int gcur = -1;

    for (int v = v0; v < v1; v++) {
        uint4 r = *((const uint4*)(g_y + (size_t)v * 64) + sub);
        int g = batch[v];                         // broadcast within 8-lane group
        if (g != gcur) {
            if (gcur >= 0) {
                int pb = gcur * 64 + sub * 8;
#pragma unroll
                for (int j = 0; j < 4; j++) {
                    float2 fx = __half22float2(*(half2*)&mx[j]);
                    float2 fn = __half22float2(*(half2*)&mn[j]);
                    atomicMaxFloat(&g_pmax[pb + 2 * j], fx.x);
                    atomicMaxFloat(&g_pmax[pb + 2 * j + 1], fx.y);
                    atomicMinFloat(&g_pmin[pb + 2 * j], fn.x);
                    atomicMinFloat(&g_pmin[pb + 2 * j + 1], fn.y);
                }
#pragma unroll
                for (int j = 0; j < 8; j++) atomicAdd(&g_psum[pb + j], psum[j]);
            }
            gcur = g;
#pragma unroll
            for (int j = 0; j < 8; j++) psum[j] = 0.f;
#pragma unroll
            for (int j = 0; j < 4; j++) { mx[j] = 0xFC00FC00u; mn[j] = 0x7C007C00u; }
        }
        half2 h0 = *(half2*)&r.x, h1 = *(half2*)&r.y;
        half2 h2 = *(half2*)&r.z, h3 = *(half2*)&r.w;
        *(half2*)&mx[0] = __hmax2(*(half2*)&mx[0], h0);
        *(half2*)&mx[1] = __hmax2(*(half2*)&mx[1], h1);
        *(half2*)&mx[2] = __hmax2(*(half2*)&mx[2], h2);
        *(half2*)&mx[3] = __hmax2(*(half2*)&mx[3], h3);
        *(half2*)&mn[0] = __hmin2(*(half2*)&mn[0], h0);
        *(half2*)&mn[1] = __hmin2(*(half2*)&mn[1], h1);
        *(half2*)&mn[2] = __hmin2(*(half2*)&mn[2], h2);
        *(half2*)&mn[3] = __hmin2(*(half2*)&mn[3], h3);
        float2 f0 = __half22float2(h0), f1 = __half22float2(h1);
        float2 f2 = __half22float2(h2), f3 = __half22float2(h3);
        psum[0] += f0.x; psum[1] += f0.y; psum[2] += f1.x; psum[3] += f1.y;
        psum[4] += f2.x; psum[5] += f2.y; psum[6] += f3.x; psum[7] += f3.y;
        sq[0] = fmaf(f0.x, f0.x, sq[0]); sq[1] = fmaf(f0.y, f0.y, sq[1]);
        sq[2] = fmaf(f1.x, f1.x, sq[2]); sq[3] = fmaf(f1.y, f1.y, sq[3]);
        sq[4] = fmaf(f2.x, f2.x, sq[4]); sq[5] = fmaf(f2.y, f2.y, sq[5]);
        sq[6] = fmaf(f3.x, f3.x, sq[6]); sq[7] = fmaf(f3.y, f3.y, sq[7]);
    }
    if (gcur >= 0) {
        int pb = gcur * 64 + sub * 8;
#pragma unroll
        for (int j = 0; j < 4; j++) {
            float2 fx = __half22float2(*(half2*)&mx[j]);
            float2 fn = __half22float2(*(half2*)&mn[j]);
            atomicMaxFloat(&g_pmax[pb + 2 * j], fx.x);
            atomicMaxFloat(&g_pmax[pb + 2 * j + 1], fx.y);
            atomicMinFloat(&g_pmin[pb + 2 * j], fn.x);
            atomicMinFloat(&g_pmin[pb + 2 * j + 1], fn.y);
        }
#pragma unroll
        for (int j = 0; j < 8; j++) atomicAdd(&g_psum[pb + j], psum[j]);
    }
#pragma unroll
    for (int j = 0; j < 8; j++) atomicAdd(&g_q2[sub * 8 + j], sq[j]);
}

// ======= finalize (s2 derived from psum) =====================================
__global__ void k_final(const float* __restrict__ gamma2, const float* __restrict__ beta2,
                        float* __restrict__ out) {
    int f = threadIdx.x;
    if (f >= 64) return;
    float s2f = 0.0f;
    for (int g = 0; g < GG; g++) s2f += g_psum[g * 64 + f];
    float mu = s2f / (float)NN;
    float var = g_q2[f] / (float)NN - mu * mu;
    float a = rsqrtf(var + EPS) * gamma2[f];
    float sh = beta2[f] - mu * a;
    for (int g = 0; g < GG; g++) {
        float mx = __int_as_float(g_pmax[g * 64 + f]);
        float mn = __int_as_float(g_pmin[g * 64 + f]);
        float chosen = (a >= 0.f) ? mx : mn;
        out[g * 128 + f] = fmaf(chosen, a, sh);
        float c = fmaxf((float)g_cnt[g], 1.f);
        out[g * 128 + 64 + f] = fmaf(g_psum[g * 64 + f] / c, a, sh);
    }
}

// ---------------- launch ----------------
extern "C" void kernel_launch(void* const* d_in, const int* in_sizes, int n_in,
                              void* d_out, int out_size) {
    const int* node_type = (const int*)d_in[0];
    const int* num_inv   = (const int*)d_in[1];
    const int* edge      = (const int*)d_in[2];
    const int* batch     = (const int*)d_in[3];
    const float* emb_type = (const float*)d_in[4];
    const float* emb_inv  = (const float*)d_in[5];
    const float* W1       = (const float*)d_in[6];
    const float* W2       = (const float*)d_in[8];
    const float* gamma1   = (const float*)d_in[10];
    const float* beta1    = (const float*)d_in[11];
    const float* gamma2   = (const float*)d_in[12];
    const float* beta2    = (const float*)d_in[13];
    float* out = (float*)d_out;

    const int* esrc = edge;
    const int* edst = edge + EE;

    void* pDeg;
    cudaGetSymbolAddress(&pDeg, g_deg);
    cudaMemsetAsync(pDeg, 0, (size_t)NN * sizeof(int));

    k_init_deg<<<NBD + 3, 256>>>(edst, batch, emb_type, emb_inv, W1);
    k_dis_scan1<<<NBS, SCAN_B>>>(node_type, num_inv);
    k_scan23<<<NBS, SCAN_B>>>();
    k_scatter_edge1<<<NBD, 256>>>(esrc, edst);
    k_stats<<<296, 256>>>();
    k_fused1<<<F1_BLOCKS, 256>>>(W2, gamma1, beta1);
    k_gather<<<1184, 256>>>();
    k_pool<<<296, 256>>>(batch);
    k_final<<<1, 64>>>(gamma2, beta2, out);
}

// round 17
// speedup vs baseline: 1.5637x; 1.5637x over previous
#include <cuda_runtime.h>
#include <cuda_fp16.h>
#include <mma.h>

using namespace nvcuda;

#define NN 500000
#define EE 2000000
#define GG 64
#define EPS 1e-5f
#define SCAN_B 512
#define NBS ((NN + SCAN_B - 1) / SCAN_B)   // 977
#define NBD ((EE + 255) / 256)             // 7813
#define NTILES ((NN + 127) / 128)          // 3907

// ---------------- scratch (device globals; no allocs allowed) ----------------
__device__ __align__(16) int    g_deg[NN];
__device__ __align__(16) float  g_dis[NN];
__device__ __align__(16) int2   g_dc[NN];
__device__ __align__(16) int    g_off[NN + 1];
__device__ __align__(16) int    g_cur[NN];
__device__ __align__(16) int    g_bsum[NBS];
__device__ __align__(16) int    g_srcs[EE];
__device__ __align__(16) float  g_S[NN * 9];
__device__ __align__(16) __half g_z1[((size_t)NN + 128) * 64];  // dis*relu(affine(S@M1))
__device__ __align__(16) __half g_y1[((size_t)NN + 128) * 64];  // z1 @ W2
__device__ __align__(16) __half g_y[(size_t)NN * 64];
__device__ __align__(16) float  g_M1[9 * 64];
__device__ __align__(16) float  g_mom[64];
__device__ __align__(16) float  g_s2[64];
__device__ __align__(16) float  g_q2[64];
__device__ __align__(16) float  g_psum[GG * 64];
__device__ __align__(16) int    g_pmax[GG * 64];
__device__ __align__(16) int    g_pmin[GG * 64];
__device__                int    g_cnt[GG];

// ---------------- helpers ----------------
__device__ __forceinline__ void atomicMaxFloat(int* addr, float v) {
    if (v >= 0.0f) atomicMax(addr, __float_as_int(v));
    else           atomicMin((unsigned int*)addr, __float_as_uint(v));
}
__device__ __forceinline__ void atomicMinFloat(int* addr, float v) {
    if (v >= 0.0f) atomicMin(addr, __float_as_int(v));
    else           atomicMax((unsigned int*)addr, __float_as_uint(v));
}
__device__ __forceinline__ void acc8(float* a, uint4 r) {
    float2 q0 = __half22float2(*(half2*)&r.x);
    float2 q1 = __half22float2(*(half2*)&r.y);
    float2 q2 = __half22float2(*(half2*)&r.z);
    float2 q3 = __half22float2(*(half2*)&r.w);
    a[0] += q0.x; a[1] += q0.y; a[2] += q1.x; a[3] += q1.y;
    a[4] += q2.x; a[5] += q2.y; a[6] += q3.x; a[7] += q3.y;
}

// ======= degree histogram + all small init + cnt + M1 prep ===================
__global__ void k_init_deg(const int* __restrict__ edst,
                           const int* __restrict__ batch,
                           const float* __restrict__ emb_type,
                           const float* __restrict__ emb_inv,
                           const float* __restrict__ W1) {
    int b = blockIdx.x;
    int tid = threadIdx.x;
    if (b < NBD) {
        int e = b * 256 + tid;
        if (e < EE) atomicAdd(&g_deg[edst[e]], 1);
        return;
    }
    int extra = b - NBD;
    if (extra == 0) {
        for (int i = tid; i < GG * 64; i += 256) {
            g_pmax[i] = 0xFF800000;
            g_pmin[i] = 0x7F800000;
            g_psum[i] = 0.0f;
        }
        if (tid < 64) { g_mom[tid] = 0.0f; g_s2[tid] = 0.0f; g_q2[tid] = 0.0f; }
    } else if (extra == 1) {
        int g = tid;
        if (g < GG) {
            int lo0 = 0, hi0 = NN;
            while (lo0 < hi0) { int m = (lo0 + hi0) >> 1; if (batch[m] < g) lo0 = m + 1; else hi0 = m; }
            int lo1 = lo0, hi1 = NN;
            while (lo1 < hi1) { int m = (lo1 + hi1) >> 1; if (batch[m] < g + 1) lo1 = m + 1; else hi1 = m; }
            g_cnt[g] = lo1 - lo0;
        }
    } else {
        for (int t = tid; t < 9 * 64; t += 256) {
            int combo = t >> 6;
            int f = t & 63;
            int ty = combo / 3, iv = combo % 3;
            float acc = 0.0f;
#pragma unroll
            for (int k = 0; k < 16; k++) {
                acc = fmaf(emb_type[ty * 16 + k], W1[k * 64 + f], acc);
                acc = fmaf(emb_inv[iv * 16 + k], W1[(16 + k) * 64 + f], acc);
            }
            g_M1[combo * 64 + f] = acc;
        }
    }
}

// ======= per-node dis/dc/S-row + block-scan of deg (scan stage 1) ============
__global__ __launch_bounds__(SCAN_B) void k_dis_scan1(const int* __restrict__ node_type,
                                                      const int* __restrict__ num_inv) {
    __shared__ int s[SCAN_B];
    int gid = blockIdx.x * SCAN_B + threadIdx.x;
    int dval = (gid < NN) ? g_deg[gid] : 0;
    if (gid < NN) {
        int d = dval + 1;
        float dis = rsqrtf((float)d);
        g_dis[gid] = dis;
        int c = node_type[gid] * 3 + num_inv[gid];
        g_dc[gid] = make_int2(__float_as_int(dis), c);
        float id = dis * dis;
#pragma unroll
        for (int t = 0; t < 9; t++) g_S[(size_t)gid * 9 + t] = (t == c) ? id : 0.0f;
    }
    s[threadIdx.x] = dval;
    __syncthreads();
    for (int o = 1; o < SCAN_B; o <<= 1) {
        int x = s[threadIdx.x];
        if (threadIdx.x >= o) x += s[threadIdx.x - o];
        __syncthreads();
        s[threadIdx.x] = x;
        __syncthreads();
    }
    if (threadIdx.x == SCAN_B - 1) g_bsum[blockIdx.x] = s[SCAN_B - 1];
}

// ======= fused scan stages 2+3 ===============================================
__global__ __launch_bounds__(SCAN_B) void k_scan23() {
    __shared__ int s[SCAN_B];
    __shared__ int red[SCAN_B];
    int acc = 0;
    for (int j = threadIdx.x; j < blockIdx.x; j += SCAN_B) acc += g_bsum[j];
    red[threadIdx.x] = acc;
    __syncthreads();
    for (int o = SCAN_B / 2; o > 0; o >>= 1) {
        if ((int)threadIdx.x < o) red[threadIdx.x] += red[threadIdx.x + o];
        __syncthreads();
    }
    int bpre = red[0];

    int gid = blockIdx.x * SCAN_B + threadIdx.x;
    int dval = (gid < NN) ? g_deg[gid] : 0;
    s[threadIdx.x] = dval;
    __syncthreads();
    for (int o = 1; o < SCAN_B; o <<= 1) {
        int x = s[threadIdx.x];
        if (threadIdx.x >= o) x += s[threadIdx.x - o];
        __syncthreads();
        s[threadIdx.x] = x;
        __syncthreads();
    }
    if (gid < NN) {
        int excl = s[threadIdx.x] - dval + bpre;
        g_off[gid] = excl;
        g_cur[gid] = excl;
        if (gid == NN - 1) g_off[NN] = excl + dval;
    }
}

// ======= CSR ticket-scatter + layer-1 bucket aggregation =====================
__global__ void k_scatter_edge1(const int* __restrict__ esrc, const int* __restrict__ edst) {
    int e = blockIdx.x * blockDim.x + threadIdx.x;
    if (e >= EE) return;
    int s = esrc[e], d = edst[e];
    int2 ds = __ldg(&g_dc[s]);
    int2 dd = __ldg(&g_dc[d]);
    int pos = atomicAdd(&g_cur[d], 1);
    g_srcs[pos] = s;
    atomicAdd(&g_S[(size_t)d * 9 + ds.y], __int_as_float(ds.x) * __int_as_float(dd.x));
}

// ======= S moments ============================================================
__global__ __launch_bounds__(256) void k_stats() {
    __shared__ float sS[256 * 9];
    __shared__ float sred[8][54];
    float m[54];
#pragma unroll
    for (int i = 0; i < 54; i++) m[i] = 0.0f;

    int tiles = (NN + 255) / 256;
    for (int t = blockIdx.x; t < tiles; t += gridDim.x) {
        int base = t * 256;
        int cnt = min(256, NN - base);
        int tot = cnt * 9;
        __syncthreads();
        for (int i = threadIdx.x; i < tot; i += 256) sS[i] = g_S[(size_t)base * 9 + i];
        __syncthreads();
        if ((int)threadIdx.x < cnt) {
            float r[9];
#pragma unroll
            for (int j = 0; j < 9; j++) r[j] = sS[threadIdx.x * 9 + j];
            int k = 9;
#pragma unroll
            for (int i = 0; i < 9; i++) {
                m[i] += r[i];
#pragma unroll
                for (int j = i; j < 9; j++) { m[k] = fmaf(r[i], r[j], m[k]); k++; }
            }
        }
    }
#pragma unroll
    for (int v = 0; v < 54; v++) {
#pragma unroll
        for (int o = 16; o > 0; o >>= 1) m[v] += __shfl_down_sync(0xffffffffu, m[v], o);
    }
    int lane = threadIdx.x & 31, warp = threadIdx.x >> 5;
    if (lane == 0) {
#pragma unroll
        for (int v = 0; v < 54; v++) sred[warp][v] = m[v];
    }
    __syncthreads();
    if (threadIdx.x < 54) {
        float acc = 0.0f;
#pragma unroll
        for (int w = 0; w < 8; w++) acc += sred[w][threadIdx.x];
        atomicAdd(&g_mom[threadIdx.x], acc);
    }
}

// ======= streaming z1 build: z1 = dis*relu(affine(S@M1)) fp16 ================
// Pure elementwise kernel — no per-tile syncs, low regs, high occupancy.
__global__ __launch_bounds__(256) void k_z1(const float* __restrict__ gamma1,
                                            const float* __restrict__ beta1) {
    __shared__ float sM1[9 * 64];
    __shared__ float sA[64], sSh[64];
    int tid = threadIdx.x;
    for (int i = tid; i < 9 * 64; i += 256) sM1[i] = g_M1[i];
    __syncthreads();
    if (tid < 64) {
        int f = tid;
        float mcol[9];
#pragma unroll
        for (int t = 0; t < 9; t++) mcol[t] = sM1[t * 64 + f];
        float mean = 0.0f;
#pragma unroll
        for (int t = 0; t < 9; t++) mean = fmaf(g_mom[t], mcol[t], mean);
        mean /= (float)NN;
        float e2 = 0.0f;
        int k = 9;
#pragma unroll
        for (int i = 0; i < 9; i++) {
#pragma unroll
            for (int j = i; j < 9; j++) {
                float term = g_mom[k++] * mcol[i] * mcol[j];
                e2 += (i == j) ? term : 2.0f * term;
            }
        }
        e2 /= (float)NN;
        float var = e2 - mean * mean;
        float a = rsqrtf(var + EPS) * gamma1[f];
        sA[f] = a;
        sSh[f] = beta1[f] - mean * a;
    }
    __syncthreads();

    int gid = blockIdx.x * 256 + tid;
    int nth = gridDim.x * 256;
    for (int idx = gid; idx < NN * 2; idx += nth) {
        int v = idx >> 1;
        int h = idx & 1;
        float dv = g_dis[v];
        float Sv[9];
#pragma unroll
        for (int t = 0; t < 9; t++) Sv[t] = g_S[(size_t)v * 9 + t];
        half2 outv[16];
#pragma unroll
        for (int j = 0; j < 16; j++) {
            int f = h * 32 + 2 * j;
            float y0 = 0.f, y1 = 0.f;
#pragma unroll
            for (int t = 0; t < 9; t++) {
                y0 = fmaf(Sv[t], sM1[t * 64 + f], y0);
                y1 = fmaf(Sv[t], sM1[t * 64 + f + 1], y1);
            }
            float z0 = dv * fmaxf(fmaf(y0, sA[f], sSh[f]), 0.f);
            float z1 = dv * fmaxf(fmaf(y1, sA[f + 1], sSh[f + 1]), 0.f);
            outv[j] = __floats2half2_rn(z0, z1);
        }
        uint4* dst = (uint4*)(g_z1 + (size_t)v * 64 + h * 32);
#pragma unroll
        for (int q = 0; q < 4; q++) dst[q] = ((uint4*)outv)[q];
    }
}

// ======= persistent wmma GEMM: y1 = z1 @ W2 (fp16 in, fp32 accum) ============
#define ZLD 72
__global__ __launch_bounds__(256) void k_gemm1(const float* __restrict__ W2) {
    __shared__ __half sW[64 * 64];
    __shared__ __align__(16) __half sZ[128 * ZLD];
    int tid = threadIdx.x;
    for (int i = tid; i < 64 * 64 / 2; i += 256) {
        float2 w = ((const float2*)W2)[i];
        ((half2*)sW)[i] = __floats2half2_rn(w.x, w.y);
    }
    int w = tid >> 5;

    for (int t = blockIdx.x; t < NTILES; t += gridDim.x) {
        int base = t * 128;
        __syncthreads();   // sW ready (first iter) / protect sZ from prior wmma
        // load z1 tile: 128 rows x 64 half = 1024 uint4, coalesced
        for (int i = tid; i < 1024; i += 256) {
            int row = i >> 3;
            int c8 = i & 7;
            uint4 val = make_uint4(0u, 0u, 0u, 0u);
            if (base + row < NN)
                val = *((const uint4*)(g_z1 + (size_t)(base + row) * 64) + c8);
            *(uint4*)(sZ + row * ZLD + c8 * 8) = val;
        }
        __syncthreads();

        wmma::fragment<wmma::accumulator, 16, 16, 16, float> cf[4];
#pragma unroll
        for (int n = 0; n < 4; n++) wmma::fill_fragment(cf[n], 0.0f);
#pragma unroll
        for (int k = 0; k < 4; k++) {
            wmma::fragment<wmma::matrix_a, 16, 16, 16, __half, wmma::row_major> af;
            wmma::load_matrix_sync(af, sZ + (w * 16) * ZLD + k * 16, ZLD);
#pragma unroll
            for (int n = 0; n < 4; n++) {
                wmma::fragment<wmma::matrix_b, 16, 16, 16, __half, wmma::row_major> bf;
                wmma::load_matrix_sync(bf, sW + (k * 16) * 64 + n * 16, 64);
                wmma::mma_sync(cf[n], af, bf, cf[n]);
            }
        }
#pragma unroll
        for (int n = 0; n < 4; n++) {
            wmma::fragment<wmma::accumulator, 16, 16, 16, __half> ch;
#pragma unroll
            for (int i = 0; i < cf[n].num_elements; i++) ch.x[i] = __float2half(cf[n].x[i]);
            wmma::store_matrix_sync(g_y1 + ((size_t)base + w * 16) * 64 + n * 16, ch, 64,
                                    wmma::mem_row_major);
        }
    }
}

// ======= CSR gather — 4 nodes/warp, MLP-4 batched row loads (R12) ============
__global__ __launch_bounds__(256) void k_gather() {
    int lane = threadIdx.x & 31;
    int sub = lane & 7;
    int grp = lane >> 3;
    int gw = (blockIdx.x * blockDim.x + threadIdx.x) >> 5;
    int nw = (gridDim.x * blockDim.x) >> 5;

    for (int v = gw * 4 + grp; v < NN; v += nw * 4) {
        uint4 raw = ((const uint4*)(g_y1 + (size_t)v * 64))[sub];
        int off0 = __ldg(&g_off[v]), off1 = __ldg(&g_off[v + 1]);
        float a[8];
        float2 p0 = __half22float2(*(half2*)&raw.x);
        float2 p1 = __half22float2(*(half2*)&raw.y);
        float2 p2 = __half22float2(*(half2*)&raw.z);
        float2 p3 = __half22float2(*(half2*)&raw.w);
        a[0] = p0.x; a[1] = p0.y; a[2] = p1.x; a[3] = p1.y;
        a[4] = p2.x; a[5] = p2.y; a[6] = p3.x; a[7] = p3.y;

        int i = off0;
        for (; i + 3 < off1; i += 4) {
            int s0 = __ldg(&g_srcs[i]);
            int s1 = __ldg(&g_srcs[i + 1]);
            int s2 = __ldg(&g_srcs[i + 2]);
            int s3 = __ldg(&g_srcs[i + 3]);
            uint4 r0 = ((const uint4*)(g_y1 + (size_t)s0 * 64))[sub];
            uint4 r1 = ((const uint4*)(g_y1 + (size_t)s1 * 64))[sub];
            uint4 r2 = ((const uint4*)(g_y1 + (size_t)s2 * 64))[sub];
            uint4 r3 = ((const uint4*)(g_y1 + (size_t)s3 * 64))[sub];
            acc8(a, r0); acc8(a, r1); acc8(a, r2); acc8(a, r3);
        }
        if (i + 1 < off1) {
            int s0 = __ldg(&g_srcs[i]);
            int s1 = __ldg(&g_srcs[i + 1]);
            uint4 r0 = ((const uint4*)(g_y1 + (size_t)s0 * 64))[sub];
            uint4 r1 = ((const uint4*)(g_y1 + (size_t)s1 * 64))[sub];
            acc8(a, r0); acc8(a, r1);
            i += 2;
        }
        if (i < off1) {
            int s0 = __ldg(&g_srcs[i]);
            uint4 r0 = ((const uint4*)(g_y1 + (size_t)s0 * 64))[sub];
            acc8(a, r0);
        }

        float dv = g_dis[v];
        half2 h0 = __floats2half2_rn(dv * a[0], dv * a[1]);
        half2 h1 = __floats2half2_rn(dv * a[2], dv * a[3]);
        half2 h2 = __floats2half2_rn(dv * a[4], dv * a[5]);
        half2 h3 = __floats2half2_rn(dv * a[6], dv * a[7]);
        int4 out;
        out.x = *(int*)&h0; out.y = *(int*)&h1;
        out.z = *(int*)&h2; out.w = *(int*)&h3;
        __stcs((int4*)(g_y + (size_t)v * 64) + sub, out);
    }
}

// ======= streaming pool + BN2 stats (R12 version) ============================
__global__ __launch_bounds__(256) void k_pool(const int* __restrict__ batch) {
    __shared__ float sS[8][64];
    __shared__ float sQ[8][64];
    int lane = threadIdx.x & 31;
    int wid = threadIdx.x >> 5;
    int gwarp = blockIdx.x * 8 + wid;
    int nwarps = gridDim.x * 8;
    int npw = (NN + nwarps - 1) / nwarps;
    int v0 = gwarp * npw;
    int v1 = min(v0 + npw, NN);
    int f0 = 2 * lane;

    float ps0 = 0.f, ps1 = 0.f;
    float mx0 = -__int_as_float(0x7F800000), mx1 = mx0;
    float mn0 = __int_as_float(0x7F800000), mn1 = mn0;
    float ss0 = 0.f, ss1 = 0.f, sq0 = 0.f, sq1 = 0.f;
    int gcur = -1;

    for (int v = v0; v < v1; v++) {
        unsigned int bits = __ldcs((const unsigned int*)(g_y + (size_t)v * 64) + lane);
        float2 f = __half22float2(*(half2*)&bits);
        int g = batch[v];
        if (g != gcur) {
            if (gcur >= 0) {
                int pb = gcur * 64 + f0;
                atomicAdd(&g_psum[pb], ps0);
                atomicAdd(&g_psum[pb + 1], ps1);
                atomicMaxFloat(&g_pmax[pb], mx0);
                atomicMaxFloat(&g_pmax[pb + 1], mx1);
                atomicMinFloat(&g_pmin[pb], mn0);
                atomicMinFloat(&g_pmin[pb + 1], mn1);
            }
            gcur = g;
            ps0 = 0.f; ps1 = 0.f;
            mx0 = -__int_as_float(0x7F800000); mx1 = mx0;
            mn0 = __int_as_float(0x7F800000); mn1 = mn0;
        }
        ps0 += f.x; ps1 += f.y;
        mx0 = fmaxf(mx0, f.x); mx1 = fmaxf(mx1, f.y);
        mn0 = fminf(mn0, f.x); mn1 = fminf(mn1, f.y);
        ss0 += f.x; ss1 += f.y;
        sq0 = fmaf(f.x, f.x, sq0); sq1 = fmaf(f.y, f.y, sq1);
    }
    if (gcur >= 0) {
        int pb = gcur * 64 + f0;
        atomicAdd(&g_psum[pb], ps0);
        atomicAdd(&g_psum[pb + 1], ps1);
        atomicMaxFloat(&g_pmax[pb], mx0);
        atomicMaxFloat(&g_pmax[pb + 1], mx1);
        atomicMinFloat(&g_pmin[pb], mn0);
        atomicMinFloat(&g_pmin[pb + 1], mn1);
    }
    sS[wid][f0] = ss0; sS[wid][f0 + 1] = ss1;
    sQ[wid][f0] = sq0; sQ[wid][f0 + 1] = sq1;
    __syncthreads();
    if (threadIdx.x < 64) {
        float as = 0.f, aq = 0.f;
#pragma unroll
        for (int w = 0; w < 8; w++) { as += sS[w][threadIdx.x]; aq += sQ[w][threadIdx.x]; }
        atomicAdd(&g_s2[threadIdx.x], as);
        atomicAdd(&g_q2[threadIdx.x], aq);
    }
}

// ======= finalize (R12) =======================================================
__global__ void k_final(const float* __restrict__ gamma2, const float* __restrict__ beta2,
                        float* __restrict__ out) {
    int f = threadIdx.x;
    if (f >= 64) return;
    float mu = g_s2[f] / (float)NN;
    float var = g_q2[f] / (float)NN - mu * mu;
    float a = rsqrtf(var + EPS) * gamma2[f];
    float sh = beta2[f] - mu * a;
    for (int g = 0; g < GG; g++) {
        float mx = __int_as_float(g_pmax[g * 64 + f]);
        float mn = __int_as_float(g_pmin[g * 64 + f]);
        float chosen = (a >= 0.f) ? mx : mn;
        out[g * 128 + f] = fmaf(chosen, a, sh);
        float c = fmaxf((float)g_cnt[g], 1.f);
        out[g * 128 + 64 + f] = fmaf(g_psum[g * 64 + f] / c, a, sh);
    }
}

// ---------------- launch ----------------
extern "C" void kernel_launch(void* const* d_in, const int* in_sizes, int n_in,
                              void* d_out, int out_size) {
    const int* node_type = (const int*)d_in[0];
    const int* num_inv   = (const int*)d_in[1];
    const int* edge      = (const int*)d_in[2];
    const int* batch     = (const int*)d_in[3];
    const float* emb_type = (const float*)d_in[4];
    const float* emb_inv  = (const float*)d_in[5];
    const float* W1       = (const float*)d_in[6];
    const float* W2       = (const float*)d_in[8];
    const float* gamma1   = (const float*)d_in[10];
    const float* beta1    = (const float*)d_in[11];
    const float* gamma2   = (const float*)d_in[12];
    const float* beta2    = (const float*)d_in[13];
    float* out = (float*)d_out;

    const int* esrc = edge;
    const int* edst = edge + EE;

    void* pDeg;
    cudaGetSymbolAddress(&pDeg, g_deg);
    cudaMemsetAsync(pDeg, 0, (size_t)NN * sizeof(int));

    k_init_deg<<<NBD + 3, 256>>>(edst, batch, emb_type, emb_inv, W1);
    k_dis_scan1<<<NBS, SCAN_B>>>(node_type, num_inv);
    k_scan23<<<NBS, SCAN_B>>>();
    k_scatter_edge1<<<NBD, 256>>>(esrc, edst);
    k_stats<<<296, 256>>>();
    k_z1<<<1184, 256>>>(gamma1, beta1);
    k_gemm1<<<1184, 256>>>(W2);
    k_gather<<<1184, 256>>>();
    k_pool<<<296, 256>>>(batch);
    k_final<<<1, 64>>>(gamma2, beta2, out);
}